// round 1
// baseline (speedup 1.0000x reference)
#include <cuda_runtime.h>
#include <cuda_bf16.h>

#define NROWS 100000
#define SDIM  1024
#define DDIM  512
#define NRBF  8
#define FEAT  20
#define THREADS 256

__global__ __launch_bounds__(THREADS, 3)
void corr_node_encoding_kernel(
    const float* __restrict__ x,
    const float* __restrict__ C,
    const unsigned char* __restrict__ mask,
    const float* __restrict__ W,       // [FEAT, DDIM]
    const float* __restrict__ bias,    // [DDIM]
    const float* __restrict__ gamma,   // [DDIM]
    const float* __restrict__ beta,    // [DDIM]
    const float* __restrict__ gatep,   // scalar
    const float* __restrict__ centers, // [NRBF]
    const float* __restrict__ widths,  // [NRBF]
    float* __restrict__ out)
{
    const int tid  = threadIdx.x;
    const int lane = tid & 31;
    const int wid  = tid >> 5;
    const int d0   = tid * 2;          // this thread owns output dims d0, d0+1

    // ---- per-thread register-resident weight slice [FEAT][2] ----
    float w[FEAT][2];
#pragma unroll
    for (int f = 0; f < FEAT; f++) {
        const float2 ww = *reinterpret_cast<const float2*>(W + f * DDIM + d0);
        w[f][0] = ww.x; w[f][1] = ww.y;
    }
    const float2 bb = *reinterpret_cast<const float2*>(bias  + d0);
    const float2 gg = *reinterpret_cast<const float2*>(gamma + d0);
    const float2 be = *reinterpret_cast<const float2*>(beta  + d0);
    const float gate = *gatep;

    __shared__ float wp[8][4];     // per-warp partials: sum, sumsq, min, max
    __shared__ float zsh[FEAT];    // feature vector z
    __shared__ float pp[8][2];     // per-warp pe partials: sum, sumsq
    __shared__ float musig[2];     // mu, rsigma
    __shared__ float cw[2 * NRBF]; // rbf centers | widths

    if (tid < NRBF) { cw[tid] = centers[tid]; cw[NRBF + tid] = widths[tid]; }

    int row = blockIdx.x;
    const int stride = gridDim.x;

    // ---- prefetch first row ----
    float4 c4 = make_float4(0.f, 0.f, 0.f, 0.f);
    float2 x2 = make_float2(0.f, 0.f);
    if (row < NROWS) {
        c4 = *reinterpret_cast<const float4*>(C + (size_t)row * SDIM + tid * 4);
        x2 = *reinterpret_cast<const float2*>(x + (size_t)row * DDIM + d0);
    }

    while (row < NROWS) {
        const int nrow = row + stride;
        const float4 cc = c4;
        const float2 xx = x2;
        // prefetch next row's C and x (overlaps DRAM latency with this row's compute)
        if (nrow < NROWS) {
            c4 = *reinterpret_cast<const float4*>(C + (size_t)nrow * SDIM + tid * 4);
            x2 = *reinterpret_cast<const float2*>(x + (size_t)nrow * DDIM + d0);
        }

        // ---- clip + local stats over 4 elements ----
        const float a0 = fminf(fmaxf(cc.x, 0.f), 1.f);
        const float a1 = fminf(fmaxf(cc.y, 0.f), 1.f);
        const float a2 = fminf(fmaxf(cc.z, 0.f), 1.f);
        const float a3 = fminf(fmaxf(cc.w, 0.f), 1.f);
        float s  = (a0 + a1) + (a2 + a3);
        float s2 = fmaf(a0, a0, fmaf(a1, a1, fmaf(a2, a2, a3 * a3)));
        float mn = fminf(fminf(a0, a1), fminf(a2, a3));
        float mx = fmaxf(fmaxf(a0, a1), fmaxf(a2, a3));

        // ---- warp reduction ----
#pragma unroll
        for (int o = 16; o; o >>= 1) {
            s  += __shfl_xor_sync(0xffffffffu, s,  o);
            s2 += __shfl_xor_sync(0xffffffffu, s2, o);
            mn  = fminf(mn, __shfl_xor_sync(0xffffffffu, mn, o));
            mx  = fmaxf(mx, __shfl_xor_sync(0xffffffffu, mx, o));
        }
        if (lane == 0) { wp[wid][0] = s; wp[wid][1] = s2; wp[wid][2] = mn; wp[wid][3] = mx; }
        __syncthreads();   // A

        // ---- warp 0: finish stats, build z[20] ----
        if (wid == 0) {
            float ss  = (lane < 8) ? wp[lane][0] :  0.f;
            float ss2 = (lane < 8) ? wp[lane][1] :  0.f;
            float wmn = (lane < 8) ? wp[lane][2] :  1e30f;
            float wmx = (lane < 8) ? wp[lane][3] : -1e30f;
#pragma unroll
            for (int o = 4; o; o >>= 1) {
                ss  += __shfl_xor_sync(0xffffffffu, ss,  o);
                ss2 += __shfl_xor_sync(0xffffffffu, ss2, o);
                wmn  = fminf(wmn, __shfl_xor_sync(0xffffffffu, wmn, o));
                wmx  = fmaxf(wmx, __shfl_xor_sync(0xffffffffu, wmx, o));
            }
            const float mean = __shfl_sync(0xffffffffu, ss,  0) * (1.f / SDIM);
            const float m2   = __shfl_sync(0xffffffffu, ss2, 0) * (1.f / SDIM);
            const float mnv  = __shfl_sync(0xffffffffu, wmn, 0);
            const float mxv  = __shfl_sync(0xffffffffu, wmx, 0);
            const float sd   = sqrtf(fmaxf(m2 - mean * mean, 0.f));
            if (lane < FEAT) {
                float zv;
                if      (lane == 0) zv = mean;
                else if (lane == 1) zv = mxv;
                else if (lane == 2) zv = mnv;
                else if (lane == 3) zv = sd;
                else {
                    const float v  = (lane < 4 + NRBF) ? mean : mxv;
                    const int   ci = (lane < 4 + NRBF) ? (lane - 4) : (lane - 4 - NRBF);
                    const float dd = (v - cw[ci]) / (cw[NRBF + ci] + 1e-6f);
                    zv = __expf(-0.5f * dd * dd);
                }
                zsh[lane] = zv;
            }
        }
        __syncthreads();   // B

        // ---- matvec: pe[d] = z @ W + b, all in registers ----
        float p0 = bb.x, p1 = bb.y;
#pragma unroll
        for (int f = 0; f < FEAT; f++) {
            const float zf = zsh[f];
            p0 = fmaf(zf, w[f][0], p0);
            p1 = fmaf(zf, w[f][1], p1);
        }

        // ---- layernorm reduction over 512 pe values ----
        float ps  = p0 + p1;
        float ps2 = fmaf(p0, p0, p1 * p1);
#pragma unroll
        for (int o = 16; o; o >>= 1) {
            ps  += __shfl_xor_sync(0xffffffffu, ps,  o);
            ps2 += __shfl_xor_sync(0xffffffffu, ps2, o);
        }
        if (lane == 0) { pp[wid][0] = ps; pp[wid][1] = ps2; }
        __syncthreads();   // C

        if (tid == 0) {
            float t = 0.f, t2 = 0.f;
#pragma unroll
            for (int i = 0; i < 8; i++) { t += pp[i][0]; t2 += pp[i][1]; }
            const float mu  = t * (1.f / DDIM);
            const float var = t2 * (1.f / DDIM) - mu * mu;
            musig[0] = mu;
            musig[1] = rsqrtf(var + 1e-5f);
        }
        __syncthreads();   // D

        const float mu = musig[0];
        const float rs = musig[1];
        const float g  = mask[row] ? 0.f : gate;
        const float o0 = xx.x + g * fmaf((p0 - mu) * rs, gg.x, be.x);
        const float o1 = xx.y + g * fmaf((p1 - mu) * rs, gg.y, be.y);
        *reinterpret_cast<float2*>(out + (size_t)row * DDIM + d0) = make_float2(o0, o1);

        row = nrow;
    }
}

extern "C" void kernel_launch(void* const* d_in, const int* in_sizes, int n_in,
                              void* d_out, int out_size)
{
    const float*         x       = (const float*)d_in[0];
    const float*         C       = (const float*)d_in[1];
    const unsigned char* mask    = (const unsigned char*)d_in[2];
    const float*         W       = (const float*)d_in[3];
    const float*         bias    = (const float*)d_in[4];
    const float*         gamma   = (const float*)d_in[5];
    const float*         beta    = (const float*)d_in[6];
    const float*         gate    = (const float*)d_in[7];
    const float*         centers = (const float*)d_in[8];
    const float*         widths  = (const float*)d_in[9];
    float*               out     = (float*)d_out;

    // 148 SMs * 3 blocks/SM = one exact wave; grid-stride inside
    corr_node_encoding_kernel<<<444, THREADS>>>(
        x, C, mask, W, bias, gamma, beta, gate, centers, widths, out);
}